// round 6
// baseline (speedup 1.0000x reference)
#include <cuda_runtime.h>
#include <cuda_fp16.h>
#include <cstdint>
#include <cstddef>

// ============================================================
// MovementPrunedLinear: out = x @ (W * blockmask)^T + bias
// x: [8192,4096] f32, W: [4096,4096] f32, bias[4096], scores[128,128]
//
// R4 finding: dense fp16 mma.sync GEMM is tensor-pipe bound at the
// legacy HMMA ceiling (~16 cyc / m16n8k16 / SMSP, ~274 TF/s).
// R5: exploit ~50% block sparsity (sigmoid(scores) > 0.1). Per n-block
// (32 outputs) compact the active k-block list; GEMM CTA = 512x32
// (one n-block per CTA), gathers active 32-col K blocks from dense
// fp16 scratch via cp.async. Halves mma work -> ~2x GEMM speedup.
// ============================================================

#define MM 8192
#define NN 4096
#define KK 4096

#define MT 512
#define NT 32
#define BK 64                     // 2 k-blocks of 32 per tile
#define STAGES 3

#define TILE_A_BYTES (MT * BK * 2)   // 65536
#define TILE_B_BYTES (NT * BK * 2)   // 4096
#define STAGE_BYTES  (TILE_A_BYTES + TILE_B_BYTES)  // 69632
#define SMEM_TOTAL   (STAGES * STAGE_BYTES)         // 208896

#define THRESH -2.19722457733621938f   // logit(0.1)

// static device scratch (allowed)
__device__ __align__(128) __half g_Xh[(size_t)MM * KK];
__device__ __align__(128) __half g_Wh[(size_t)NN * KK];
__device__ int g_idx[128 * 128];   // per n-block active k-block list (padded even)
__device__ int g_cntp[128];        // padded-even active count per n-block

// ---------------- PTX helpers (compute_103-legal) ----------------
static __device__ __forceinline__ uint32_t smem_u32(const void* p) {
    return (uint32_t)__cvta_generic_to_shared(p);
}
static __device__ __forceinline__ void cp16(uint32_t dst, const void* src) {
    asm volatile("cp.async.cg.shared.global [%0], [%1], 16;" :: "r"(dst), "l"(src));
}
static __device__ __forceinline__ void cp_commit() {
    asm volatile("cp.async.commit_group;" ::: "memory");
}
static __device__ __forceinline__ void cp_wait1() {
    asm volatile("cp.async.wait_group 1;" ::: "memory");
}
static __device__ __forceinline__ void ldsm4(uint32_t& r0, uint32_t& r1,
                                             uint32_t& r2, uint32_t& r3, uint32_t a) {
    asm volatile("ldmatrix.sync.aligned.m8n8.x4.shared.b16 {%0,%1,%2,%3}, [%4];"
                 : "=r"(r0), "=r"(r1), "=r"(r2), "=r"(r3) : "r"(a));
}
static __device__ __forceinline__ void mma16816(float* d, const uint32_t* a,
                                                const uint32_t* b) {
    asm volatile(
        "mma.sync.aligned.m16n8k16.row.col.f32.f16.f16.f32 "
        "{%0,%1,%2,%3}, {%4,%5,%6,%7}, {%8,%9}, {%0,%1,%2,%3};"
        : "+f"(d[0]), "+f"(d[1]), "+f"(d[2]), "+f"(d[3])
        : "r"(a[0]), "r"(a[1]), "r"(a[2]), "r"(a[3]), "r"(b[0]), "r"(b[1]));
}

// ---------------- conversion kernels ----------------
__global__ void __launch_bounds__(256) cvt_x_kernel(const float* __restrict__ x) {
    size_t i = ((size_t)blockIdx.x * 256 + threadIdx.x) * 8;
    float4 a = *reinterpret_cast<const float4*>(x + i);
    float4 b = *reinterpret_cast<const float4*>(x + i + 4);
    __half2 h0 = __floats2half2_rn(a.x, a.y);
    __half2 h1 = __floats2half2_rn(a.z, a.w);
    __half2 h2 = __floats2half2_rn(b.x, b.y);
    __half2 h3 = __floats2half2_rn(b.z, b.w);
    uint4 o;
    o.x = *reinterpret_cast<uint32_t*>(&h0);
    o.y = *reinterpret_cast<uint32_t*>(&h1);
    o.z = *reinterpret_cast<uint32_t*>(&h2);
    o.w = *reinterpret_cast<uint32_t*>(&h3);
    *reinterpret_cast<uint4*>(g_Xh + i) = o;
}

__global__ void __launch_bounds__(256) cvt_w_kernel(const float* __restrict__ w,
                                                    const float* __restrict__ scores) {
    size_t i = ((size_t)blockIdx.x * 256 + threadIdx.x) * 8;
    int orow = (int)(i >> 12);
    int icol = (int)(i & 4095);
    float s = scores[(orow >> 5) * 128 + (icol >> 5)];
    bool active = s > THRESH;
    float4 a = *reinterpret_cast<const float4*>(w + i);
    float4 b = *reinterpret_cast<const float4*>(w + i + 4);
    if (!active) {
        a = make_float4(0.f, 0.f, 0.f, 0.f);
        b = make_float4(0.f, 0.f, 0.f, 0.f);
    }
    __half2 h0 = __floats2half2_rn(a.x, a.y);
    __half2 h1 = __floats2half2_rn(a.z, a.w);
    __half2 h2 = __floats2half2_rn(b.x, b.y);
    __half2 h3 = __floats2half2_rn(b.z, b.w);
    uint4 o;
    o.x = *reinterpret_cast<uint32_t*>(&h0);
    o.y = *reinterpret_cast<uint32_t*>(&h1);
    o.z = *reinterpret_cast<uint32_t*>(&h2);
    o.w = *reinterpret_cast<uint32_t*>(&h3);
    *reinterpret_cast<uint4*>(g_Wh + i) = o;
}

// Per n-block active k-block compaction. grid=128 blocks, 128 threads.
__global__ void __launch_bounds__(128) mask_kernel(const float* __restrict__ scores) {
    const int nb = blockIdx.x;
    const int j = threadIdx.x;      // k-block index 0..127
    const int w = j >> 5, l = j & 31;
    const bool act = scores[nb * 128 + j] > THRESH;
    __shared__ uint32_t wb[4];
    __shared__ int wfi[4];
    uint32_t b = __ballot_sync(0xffffffffu, act);
    uint32_t ib = ~b;
    if (l == 0) {
        wb[w] = b;
        wfi[w] = ib ? (w * 32 + __ffs(ib) - 1) : (1 << 30);  // first inactive in warp
    }
    __syncthreads();
    int pre = __popc(b & ((1u << l) - 1u));
    for (int k = 0; k < w; k++) pre += __popc(wb[k]);
    if (act) g_idx[nb * 128 + pre] = j;
    if (j == 0) {
        int cnt = __popc(wb[0]) + __popc(wb[1]) + __popc(wb[2]) + __popc(wb[3]);
        if (cnt & 1) {
            // pad with an inactive block (its g_Wh entries are zero)
            int fi = min(min(wfi[0], wfi[1]), min(wfi[2], wfi[3]));
            g_idx[nb * 128 + cnt] = fi;
        }
        g_cntp[nb] = cnt + (cnt & 1);
    }
}

// ---------------- block-sparse GEMM ----------------
// CTA 512x32 (one n-block). 8 warps, warp tile 64x32. BK=64 = 2 active
// k-blocks gathered via g_idx. SW128 swizzle, 3-stage cp.async pipeline.
__global__ void __launch_bounds__(256, 1) gemm_kernel(const float* __restrict__ bias,
                                                      float* __restrict__ out) {
    extern __shared__ char smem[];
    __shared__ int sIdx[128];
    __shared__ int sT;
    const uint32_t sb = smem_u32(smem);
    const int tid = threadIdx.x;
    const int wid = tid >> 5;
    const int lid = tid & 31;
    const int nb = blockIdx.x;          // n-block (32 cols)
    const int m0 = blockIdx.y * MT;

    if (tid < 128) sIdx[tid] = g_idx[nb * 128 + tid];
    if (tid == 0) sT = g_cntp[nb] >> 1;   // K-tiles of 2 blocks
    __syncthreads();
    const int T = sT;

    // -------- loader geometry --------
    // A: thread t loads rows t and t+256, 8 chunks of 16B each.
    // B: thread t loads row t>>3, chunk t&7.
    const char* aRow0 = (const char*)(g_Xh + (size_t)(m0 + tid) * KK);
    const char* aRow1 = (const char*)(g_Xh + (size_t)(m0 + tid + 256) * KK);
    const int sx = tid & 7;                       // swizzle term (same for both rows)
    const uint32_t aD0 = (uint32_t)(tid * 128);
    const uint32_t aD1 = (uint32_t)((tid + 256) * 128);
    const int bn = tid >> 3, bc = tid & 7;
    const char* bRow = (const char*)(g_Wh + (size_t)(nb * 32 + bn) * KK);
    const uint32_t bD = (uint32_t)(bn * 128 + ((bc ^ (bn & 7)) << 4));

    // -------- ldmatrix geometry --------
    const int arow = wid * 64 + (lid & 15);       // +mi*16 keeps (&7) invariant
    const int acs = lid >> 4;
    const uint32_t aBB = (uint32_t)(arow * 128);
    const uint32_t ax = (uint32_t)(arow & 7);
    const int brow = (lid & 7) + ((lid >> 4) << 3);
    const int bcs = (lid >> 3) & 1;
    const uint32_t bBB = (uint32_t)(brow * 128);
    const uint32_t bx = (uint32_t)(brow & 7);

    float acc[4][4][4];
#pragma unroll
    for (int mi = 0; mi < 4; mi++)
#pragma unroll
        for (int nj = 0; nj < 4; nj++)
#pragma unroll
            for (int c = 0; c < 4; c++) acc[mi][nj][c] = 0.0f;

    // -------- issue one K-tile's loads into a stage buffer --------
    auto issue = [&](int kt, uint32_t base) {
        const int i0 = sIdx[2 * kt] * 64;         // byte offset of k-block 0
        const int i1 = sIdx[2 * kt + 1] * 64;
#pragma unroll
        for (int c = 0; c < 8; c++) {
            const int coff = (c < 4) ? (i0 + c * 16) : (i1 + (c - 4) * 16);
            const uint32_t d = (uint32_t)((c ^ sx) << 4);
            cp16(base + aD0 + d, aRow0 + coff);
            cp16(base + aD1 + d, aRow1 + coff);
        }
        const int bcoff = (bc < 4) ? (i0 + bc * 16) : (i1 + (bc - 4) * 16);
        cp16(base + TILE_A_BYTES + bD, bRow + bcoff);
    };

    // -------- prologue: tiles 0,1 --------
#pragma unroll
    for (int s = 0; s < 2; s++) {
        if (s < T) issue(s, sb + s * STAGE_BYTES);
        cp_commit();
    }

#pragma unroll 1
    for (int t = 0; t < T; t++) {
        cp_wait1();
        __syncthreads();

        if (t + 2 < T) issue(t + 2, sb + ((t + 2) % STAGES) * STAGE_BYTES);
        cp_commit();

        const uint32_t aTile = sb + (t % STAGES) * STAGE_BYTES;
        const uint32_t bTile = aTile + TILE_A_BYTES;
#pragma unroll
        for (int ks = 0; ks < 4; ks++) {
            uint32_t afrag[4][4];
#pragma unroll
            for (int mi = 0; mi < 4; mi++) {
                uint32_t addr = aTile + aBB + mi * (16 * 128) +
                                ((((uint32_t)(ks * 2 + acs)) ^ ax) << 4);
                ldsm4(afrag[mi][0], afrag[mi][1], afrag[mi][2], afrag[mi][3], addr);
            }
            uint32_t bfrag[4][2];
#pragma unroll
            for (int ni = 0; ni < 2; ni++) {
                uint32_t r0, r1, r2, r3;
                uint32_t addr = bTile + bBB + ni * (16 * 128) +
                                ((((uint32_t)(ks * 2 + bcs)) ^ bx) << 4);
                ldsm4(r0, r1, r2, r3, addr);
                bfrag[2 * ni][0] = r0; bfrag[2 * ni][1] = r1;
                bfrag[2 * ni + 1][0] = r2; bfrag[2 * ni + 1][1] = r3;
            }
#pragma unroll
            for (int mi = 0; mi < 4; mi++)
#pragma unroll
                for (int nj = 0; nj < 4; nj++)
                    mma16816(acc[mi][nj], afrag[mi], bfrag[nj]);
        }
    }

    // -------- epilogue --------
    const int qr = lid >> 2;
    const int qc = lid & 3;
    const int colBase = nb * 32 + qc * 2;
#pragma unroll
    for (int nj = 0; nj < 4; nj++) {
        const int col = colBase + nj * 8;
        const float b0 = __ldg(bias + col);
        const float b1 = __ldg(bias + col + 1);
#pragma unroll
        for (int mi = 0; mi < 4; mi++) {
            const int row = m0 + wid * 64 + mi * 16 + qr;
            float2 v0 = make_float2(acc[mi][nj][0] + b0, acc[mi][nj][1] + b1);
            float2 v1 = make_float2(acc[mi][nj][2] + b0, acc[mi][nj][3] + b1);
            *reinterpret_cast<float2*>(out + (size_t)row * NN + col) = v0;
            *reinterpret_cast<float2*>(out + (size_t)(row + 8) * NN + col) = v1;
        }
    }
}

// ---------------- launch ----------------
extern "C" void kernel_launch(void* const* d_in, const int* in_sizes, int n_in,
                              void* d_out, int out_size) {
    const float* x      = (const float*)d_in[0];
    const float* weight = (const float*)d_in[1];
    const float* bias   = (const float*)d_in[2];
    const float* scores = (const float*)d_in[3];
    float* out = (float*)d_out;

    cvt_x_kernel<<<16384, 256>>>(x);
    cvt_w_kernel<<<8192, 256>>>(weight, scores);
    mask_kernel<<<128, 128>>>(scores);

    cudaFuncSetAttribute(gemm_kernel, cudaFuncAttributeMaxDynamicSharedMemorySize, SMEM_TOTAL);
    // nb fastest -> consecutive CTAs share the same A m-tile (L2 reuse)
    gemm_kernel<<<dim3(128, MM / MT, 1), 256, SMEM_TOTAL>>>(bias, out);
}